// round 5
// baseline (speedup 1.0000x reference)
#include <cuda_runtime.h>
#include <cuda_bf16.h>
#include <math.h>
#include <stdint.h>

#define D     64
#define TM    64        // x rows per CTA
#define KP    128       // prototypes
#define NTH   256
#define ROWB  384       // bytes per B row (192 bf16: chunks [hi|hi|lo])

#define SM_B   0
#define SM_P2  49152
#define SM_DYN (SM_P2 + 512)

// Precomputed, swizzled bf16 B image + p^2 (written by setup_kernel)
__device__ __align__(16) uint32_t g_B[KP * ROWB / 4];   // 49152 B
__device__ float g_p2[KP];

static __device__ __forceinline__ uint32_t sw(uint32_t off) {
    return off ^ ((off >> 3) & 0x70);
}

static __device__ __forceinline__ uint32_t smem_u32(const void* p) {
    uint32_t a;
    asm("{ .reg .u64 t; cvta.to.shared.u64 t, %1; cvt.u32.u64 %0, t; }" : "=r"(a) : "l"(p));
    return a;
}

static __device__ __forceinline__ void ldsm_x4(uint32_t* r, uint32_t addr) {
    asm volatile("ldmatrix.sync.aligned.m8n8.x4.shared.b16 {%0,%1,%2,%3}, [%4];"
                 : "=r"(r[0]), "=r"(r[1]), "=r"(r[2]), "=r"(r[3]) : "r"(addr));
}

static __device__ __forceinline__ void mma_bf16(float* c, const uint32_t* a,
                                                uint32_t b0, uint32_t b1) {
    asm volatile(
        "mma.sync.aligned.m16n8k16.row.col.f32.bf16.bf16.f32 "
        "{%0,%1,%2,%3}, {%4,%5,%6,%7}, {%8,%9}, {%0,%1,%2,%3};"
        : "+f"(c[0]), "+f"(c[1]), "+f"(c[2]), "+f"(c[3])
        : "r"(a[0]), "r"(a[1]), "r"(a[2]), "r"(a[3]), "r"(b0), "r"(b1));
}

static __device__ __forceinline__ void split2(float v0, float v1,
                                              uint32_t& hi, uint32_t& lo) {
    __nv_bfloat162 h = __floats2bfloat162_rn(v0, v1);
    float r0 = v0 - __bfloat162float(__low2bfloat16(h));
    float r1 = v1 - __bfloat162float(__high2bfloat16(h));
    __nv_bfloat162 l = __floats2bfloat162_rn(r0, r1);
    hi = *reinterpret_cast<uint32_t*>(&h);
    lo = *reinterpret_cast<uint32_t*>(&l);
}

static __device__ __forceinline__ float epi(float xy, float x2, float Bv, float p2) {
    const float A = 1.0f + p2 - 2.0f * xy;
    float num2 = A * A * x2 - 2.0f * A * Bv * xy + Bv * Bv * p2;
    num2 = fmaxf(num2, 1e-30f);
    const float den = fmaxf(1.0f - 2.0f * xy + x2 * p2, 1e-15f);
    float s = num2 * rsqrtf(num2);                  // sqrt(num2)
    s = fminf(s, 0.99999f * den);                   // z <= 1 - 1e-5
    const float dist = (__log2f(den + s) - __log2f(den - s)) * 0.6931471805599453f;
    return -dist * dist;
}

// ---------------------------------------------------------------------------
// Setup: project prototypes, p^2, and bake the swizzled bf16 B image.
// ---------------------------------------------------------------------------
__global__ void setup_kernel(const float* __restrict__ proto) {
    const int k = threadIdx.x;   // one prototype per thread (128 threads)
    const float4* p4 = (const float4*)(proto) + (size_t)k * (D / 4);
    float s = 0.f;
    #pragma unroll
    for (int i = 0; i < D / 4; ++i) {
        float4 v = p4[i];
        s += v.x * v.x + v.y * v.y + v.z * v.z + v.w * v.w;
    }
    const float n  = fmaxf(sqrtf(s), 1e-15f);
    const float sc = fminf(1.0f, 0.999f / n);       // (1-BALL_EPS)/sqrt(c)
    g_p2[k] = s * sc * sc;

    const float2* p2p = (const float2*)(proto) + (size_t)k * (D / 2);
    #pragma unroll
    for (int i = 0; i < D / 2; ++i) {
        float2 v = p2p[i];
        uint32_t hi, lo;
        split2(v.x * sc, v.y * sc, hi, lo);
        uint32_t base = (uint32_t)k * ROWB + (uint32_t)i * 4;
        g_B[sw(base)       >> 2] = hi;   // chunk 0: hi
        g_B[sw(base + 128) >> 2] = hi;   // chunk 1: hi
        g_B[sw(base + 256) >> 2] = lo;   // chunk 2: lo
    }
}

// ---------------------------------------------------------------------------
__global__ void __launch_bounds__(NTH)
geo_kernel(const float* __restrict__ x, float* __restrict__ out) {
    extern __shared__ char sm[];
    const uint32_t smb = smem_u32(sm);
    float* p2_s = (float*)(sm + SM_P2);

    const int tid  = threadIdx.x;
    const int wid  = tid >> 5;
    const int lane = tid & 31;
    const int n0   = blockIdx.x * TM;

    // ---- B image + p2: verbatim copy (swizzle baked in) ----
    {
        const uint4* gB4 = (const uint4*)g_B;
        uint4*       sB4 = (uint4*)sm;
        #pragma unroll
        for (int it = 0; it < (KP * ROWB / 16) / NTH; ++it)   // 12 iters
            sB4[it * NTH + tid] = gB4[it * NTH + tid];
        if (tid < KP) p2_s[tid] = g_p2[tid];
    }

    // ---- A fragments: global -> registers, split-bf16, exact x2 ----
    const int wm = wid & 3;
    const int wn = wid >> 2;
    const int r0 = wm * 16 + (lane >> 2);
    const float* xr0 = x + (size_t)(n0 + r0) * D + 2 * (lane & 3);
    const float* xr1 = xr0 + 8 * D;

    uint32_t ahi[16], alo[16];
    float s0 = 0.f, s1 = 0.f;
    #pragma unroll
    for (int t = 0; t < 4; ++t) {
        float2 v00 = *(const float2*)(xr0 + t * 16);        // (r0,  k=16t+c)
        float2 v10 = *(const float2*)(xr1 + t * 16);        // (r0+8,k=16t+c)
        float2 v01 = *(const float2*)(xr0 + t * 16 + 8);    // (r0,  k+8)
        float2 v11 = *(const float2*)(xr1 + t * 16 + 8);    // (r0+8,k+8)
        s0 += v00.x * v00.x + v00.y * v00.y + v01.x * v01.x + v01.y * v01.y;
        s1 += v10.x * v10.x + v10.y * v10.y + v11.x * v11.x + v11.y * v11.y;
        split2(v00.x, v00.y, ahi[4 * t + 0], alo[4 * t + 0]);  // a0
        split2(v10.x, v10.y, ahi[4 * t + 1], alo[4 * t + 1]);  // a1
        split2(v01.x, v01.y, ahi[4 * t + 2], alo[4 * t + 2]);  // a2
        split2(v11.x, v11.y, ahi[4 * t + 3], alo[4 * t + 3]);  // a3
    }
    s0 += __shfl_xor_sync(0xFFFFFFFFu, s0, 1);
    s0 += __shfl_xor_sync(0xFFFFFFFFu, s0, 2);
    s1 += __shfl_xor_sync(0xFFFFFFFFu, s1, 1);
    s1 += __shfl_xor_sync(0xFFFFFFFFu, s1, 2);
    const float x2a = s0, x2b = s1;

    __syncthreads();

    // ---- MMA: 12 k-steps over concatenated K=192 (A=[hi,lo,hi], B=[hi,hi,lo]) ----
    const int g     = lane >> 3;
    const int nOffB = ((g & 2) ? 8 : 0) + (lane & 7);
    const int kB    = (g & 1) * 8;

    float acc[8][4];
    #pragma unroll
    for (int j = 0; j < 8; ++j)
        #pragma unroll
        for (int u = 0; u < 4; ++u) acc[j][u] = 0.f;

    #pragma unroll
    for (int ks = 0; ks < 12; ++ks) {
        const uint32_t* a = (ks < 4) ? &ahi[4 * ks]
                          : (ks < 8) ? &alo[4 * (ks - 4)]
                                     : &ahi[4 * (ks - 8)];
        const int kg = ks * 16;
        #pragma unroll
        for (int nb = 0; nb < 4; ++nb) {
            const int nrow = wn * 64 + nb * 16 + nOffB;
            uint32_t b[4];
            ldsm_x4(b, smb + SM_B + sw((uint32_t)nrow * ROWB + (uint32_t)(kg + kB) * 2));
            mma_bf16(acc[2 * nb],     a, b[0], b[1]);
            mma_bf16(acc[2 * nb + 1], a, b[2], b[3]);
        }
    }

    // ---- epilogue straight from accumulators ----
    {
        const float Ba = 1.0f - x2a;
        const float Bb = 1.0f - x2b;
        float* orowa = out + (size_t)(n0 + r0) * KP;
        float* orowb = orowa + 8 * KP;

        #pragma unroll
        for (int j = 0; j < 8; ++j) {
            const int c = wn * 64 + j * 8 + 2 * (lane & 3);
            const float2 p2 = *(const float2*)&p2_s[c];
            float2 oa, ob;
            oa.x = epi(acc[j][0], x2a, Ba, p2.x);
            oa.y = epi(acc[j][1], x2a, Ba, p2.y);
            ob.x = epi(acc[j][2], x2b, Bb, p2.x);
            ob.y = epi(acc[j][3], x2b, Bb, p2.y);
            *(float2*)(orowa + c) = oa;
            *(float2*)(orowb + c) = ob;
        }
    }
}

// ---------------------------------------------------------------------------
extern "C" void kernel_launch(void* const* d_in, const int* in_sizes, int n_in,
                              void* d_out, int out_size) {
    const float* x;
    const float* proto;
    int xs;
    if (in_sizes[0] == KP * D) {
        proto = (const float*)d_in[0];
        x     = (const float*)d_in[1];
        xs    = in_sizes[1];
    } else {
        x     = (const float*)d_in[0];
        proto = (const float*)d_in[1];
        xs    = in_sizes[0];
    }
    const int N = xs / D;  // 16384
    float* out = (float*)d_out;

    setup_kernel<<<1, KP>>>(proto);
    cudaFuncSetAttribute(geo_kernel, cudaFuncAttributeMaxDynamicSharedMemorySize, SM_DYN);
    geo_kernel<<<N / TM, NTH, SM_DYN>>>(x, out);
}

// round 6
// speedup vs baseline: 1.4320x; 1.4320x over previous
#include <cuda_runtime.h>
#include <cuda_bf16.h>
#include <math.h>
#include <stdint.h>

#define D     64
#define TM    64        // x rows per CTA
#define KP    128       // prototypes
#define NTH   256
#define ROWB  384       // bytes per B row (192 bf16: chunks [hi|hi|lo])

// smem layout
#define SM_B   0                      // 128 x 384B = 49152
#define SM_P2  49152                  // 128 floats
#define SM_PS  (SM_P2 + 512)          // 128 floats
#define SM_DYN (SM_PS + 512)

static __device__ __forceinline__ uint32_t sw(uint32_t off) {
    return off ^ ((off >> 3) & 0x70);
}

static __device__ __forceinline__ uint32_t smem_u32(const void* p) {
    uint32_t a;
    asm("{ .reg .u64 t; cvta.to.shared.u64 t, %1; cvt.u32.u64 %0, t; }" : "=r"(a) : "l"(p));
    return a;
}

static __device__ __forceinline__ void ldsm_x4(uint32_t* r, uint32_t addr) {
    asm volatile("ldmatrix.sync.aligned.m8n8.x4.shared.b16 {%0,%1,%2,%3}, [%4];"
                 : "=r"(r[0]), "=r"(r[1]), "=r"(r[2]), "=r"(r[3]) : "r"(addr));
}

static __device__ __forceinline__ void mma_bf16(float* c, const uint32_t* a,
                                                uint32_t b0, uint32_t b1) {
    asm volatile(
        "mma.sync.aligned.m16n8k16.row.col.f32.bf16.bf16.f32 "
        "{%0,%1,%2,%3}, {%4,%5,%6,%7}, {%8,%9}, {%0,%1,%2,%3};"
        : "+f"(c[0]), "+f"(c[1]), "+f"(c[2]), "+f"(c[3])
        : "r"(a[0]), "r"(a[1]), "r"(a[2]), "r"(a[3]), "r"(b0), "r"(b1));
}

static __device__ __forceinline__ void split2(float v0, float v1,
                                              uint32_t& hi, uint32_t& lo) {
    __nv_bfloat162 h = __floats2bfloat162_rn(v0, v1);
    float r0 = v0 - __bfloat162float(__low2bfloat16(h));
    float r1 = v1 - __bfloat162float(__high2bfloat16(h));
    __nv_bfloat162 l = __floats2bfloat162_rn(r0, r1);
    hi = *reinterpret_cast<uint32_t*>(&h);
    lo = *reinterpret_cast<uint32_t*>(&l);
}

static __device__ __forceinline__ float epi(float xy, float x2, float Bv, float p2) {
    const float A = 1.0f + p2 - 2.0f * xy;
    float num2 = A * A * x2 - 2.0f * A * Bv * xy + Bv * Bv * p2;
    num2 = fmaxf(num2, 1e-30f);
    const float den = fmaxf(1.0f - 2.0f * xy + x2 * p2, 1e-15f);
    float s = num2 * rsqrtf(num2);                  // sqrt(num2)
    s = fminf(s, 0.99999f * den);                   // z <= 1 - 1e-5
    const float dist = (__log2f(den + s) - __log2f(den - s)) * 0.6931471805599453f;
    return -dist * dist;
}

// ---------------------------------------------------------------------------
// Single fused kernel. Per CTA: 64 x-rows vs all 128 prototypes.
//  A: global -> registers, split-bf16 in regs (no smem, no ldmatrix)
//  B: per-CTA redundant projection + split-bf16 into swizzled smem
//  MMA: 12 x m16n8k16 over concatenated K=192 (A=[hi,lo,hi], B=[hi,hi,lo])
// ---------------------------------------------------------------------------
__global__ void __launch_bounds__(NTH)
geo_kernel(const float* __restrict__ x, const float* __restrict__ proto,
           float* __restrict__ out) {
    extern __shared__ char sm[];
    const uint32_t smb = smem_u32(sm);
    float* p2_s = (float*)(sm + SM_P2);
    float* ps_s = (float*)(sm + SM_PS);

    const int tid  = threadIdx.x;
    const int wid  = tid >> 5;
    const int lane = tid & 31;
    const int n0   = blockIdx.x * TM;

    // ---- A path: issue x loads first (in flight during B conversion) ----
    const int wm = wid & 3;
    const int wn = wid >> 2;
    const int r0 = wm * 16 + (lane >> 2);
    const float* xr0 = x + (size_t)(n0 + r0) * D + 2 * (lane & 3);
    const float* xr1 = xr0 + 8 * D;

    float2 v00[4], v10[4], v01[4], v11[4];
    #pragma unroll
    for (int t = 0; t < 4; ++t) {
        v00[t] = *(const float2*)(xr0 + t * 16);        // (r0,   k=16t+c)
        v10[t] = *(const float2*)(xr1 + t * 16);        // (r0+8, k=16t+c)
        v01[t] = *(const float2*)(xr0 + t * 16 + 8);    // (r0,   k+8)
        v11[t] = *(const float2*)(xr1 + t * 16 + 8);    // (r0+8, k+8)
    }

    // ---- B phase 0: prototype projection scale + p^2 (tid < 128) ----
    if (tid < KP) {
        const float4* p4 = (const float4*)(proto) + (size_t)tid * (D / 4);
        float s = 0.f;
        #pragma unroll
        for (int i = 0; i < D / 4; ++i) {
            float4 v = p4[i];
            s += v.x * v.x + v.y * v.y + v.z * v.z + v.w * v.w;
        }
        const float n  = fmaxf(sqrtf(s), 1e-15f);
        const float sc = fminf(1.0f, 0.999f / n);   // (1-BALL_EPS)/sqrt(c)
        ps_s[tid] = sc;
        p2_s[tid] = s * sc * sc;
    }
    __syncthreads();

    // ---- B phase 1: split-bf16 conversion into swizzled smem ----
    {
        const float2* ps = (const float2*)(proto);
        #pragma unroll
        for (int it = 0; it < (KP * D / 2) / NTH; ++it) {   // 16 iters
            int idx = it * NTH + tid;
            int row = idx >> 5;        // 32 float2 per proto row
            int kp  = idx & 31;
            float sc = ps_s[row];
            float2 v = ps[row * 32 + kp];
            uint32_t hi, lo;
            split2(v.x * sc, v.y * sc, hi, lo);
            uint32_t base = (uint32_t)row * ROWB + (uint32_t)kp * 4;
            *(uint32_t*)(sm + SM_B + sw(base))       = hi;  // chunk 0: hi
            *(uint32_t*)(sm + SM_B + sw(base + 128)) = hi;  // chunk 1: hi
            *(uint32_t*)(sm + SM_B + sw(base + 256)) = lo;  // chunk 2: lo
        }
    }

    // ---- A: in-register split + exact x^2 via shuffles ----
    uint32_t ahi[16], alo[16];
    float s0 = 0.f, s1 = 0.f;
    #pragma unroll
    for (int t = 0; t < 4; ++t) {
        s0 += v00[t].x * v00[t].x + v00[t].y * v00[t].y +
              v01[t].x * v01[t].x + v01[t].y * v01[t].y;
        s1 += v10[t].x * v10[t].x + v10[t].y * v10[t].y +
              v11[t].x * v11[t].x + v11[t].y * v11[t].y;
        split2(v00[t].x, v00[t].y, ahi[4 * t + 0], alo[4 * t + 0]);
        split2(v10[t].x, v10[t].y, ahi[4 * t + 1], alo[4 * t + 1]);
        split2(v01[t].x, v01[t].y, ahi[4 * t + 2], alo[4 * t + 2]);
        split2(v11[t].x, v11[t].y, ahi[4 * t + 3], alo[4 * t + 3]);
    }
    s0 += __shfl_xor_sync(0xFFFFFFFFu, s0, 1);
    s0 += __shfl_xor_sync(0xFFFFFFFFu, s0, 2);
    s1 += __shfl_xor_sync(0xFFFFFFFFu, s1, 1);
    s1 += __shfl_xor_sync(0xFFFFFFFFu, s1, 2);
    const float x2a = s0, x2b = s1;

    __syncthreads();

    // ---- MMA: 12 k-steps (A chunk order hi, lo, hi) ----
    const int g     = lane >> 3;
    const int nOffB = ((g & 2) ? 8 : 0) + (lane & 7);
    const int kB    = (g & 1) * 8;

    float acc[8][4];
    #pragma unroll
    for (int j = 0; j < 8; ++j)
        #pragma unroll
        for (int u = 0; u < 4; ++u) acc[j][u] = 0.f;

    #pragma unroll
    for (int ks = 0; ks < 12; ++ks) {
        const uint32_t* a = (ks < 4) ? &ahi[4 * ks]
                          : (ks < 8) ? &alo[4 * (ks - 4)]
                                     : &ahi[4 * (ks - 8)];
        const int kg = ks * 16;
        #pragma unroll
        for (int nb = 0; nb < 4; ++nb) {
            const int nrow = wn * 64 + nb * 16 + nOffB;
            uint32_t b[4];
            ldsm_x4(b, smb + SM_B + sw((uint32_t)nrow * ROWB + (uint32_t)(kg + kB) * 2));
            mma_bf16(acc[2 * nb],     a, b[0], b[1]);
            mma_bf16(acc[2 * nb + 1], a, b[2], b[3]);
        }
    }

    // ---- epilogue straight from accumulators ----
    {
        const float Ba = 1.0f - x2a;
        const float Bb = 1.0f - x2b;
        float* orowa = out + (size_t)(n0 + r0) * KP;
        float* orowb = orowa + 8 * KP;

        #pragma unroll
        for (int j = 0; j < 8; ++j) {
            const int c = wn * 64 + j * 8 + 2 * (lane & 3);
            const float2 p2 = *(const float2*)&p2_s[c];
            float2 oa, ob;
            oa.x = epi(acc[j][0], x2a, Ba, p2.x);
            oa.y = epi(acc[j][1], x2a, Ba, p2.y);
            ob.x = epi(acc[j][2], x2b, Bb, p2.x);
            ob.y = epi(acc[j][3], x2b, Bb, p2.y);
            *(float2*)(orowa + c) = oa;
            *(float2*)(orowb + c) = ob;
        }
    }
}

// ---------------------------------------------------------------------------
extern "C" void kernel_launch(void* const* d_in, const int* in_sizes, int n_in,
                              void* d_out, int out_size) {
    const float* x;
    const float* proto;
    int xs;
    if (in_sizes[0] == KP * D) {
        proto = (const float*)d_in[0];
        x     = (const float*)d_in[1];
        xs    = in_sizes[1];
    } else {
        x     = (const float*)d_in[0];
        proto = (const float*)d_in[1];
        xs    = in_sizes[0];
    }
    const int N = xs / D;  // 16384
    float* out = (float*)d_out;

    cudaFuncSetAttribute(geo_kernel, cudaFuncAttributeMaxDynamicSharedMemorySize, SM_DYN);
    geo_kernel<<<N / TM, NTH, SM_DYN>>>(x, proto, out);
}